// round 4
// baseline (speedup 1.0000x reference)
#include <cuda_runtime.h>
#include <cuda_bf16.h>
#include <mma.h>

using namespace nvcuda;

#define D_EMBED 1024
#define D_HEAD  128
#define BATCH   4
#define SEQ     4096
#define M_TOTAL (BATCH * SEQ)
#define QK_SCALE (1.0f / 362.03867196751236f)   // 1/(sqrt(128)*sqrt(1024))
#define NT (SEQ / 64)                            // 64 k-tiles

// Scratch: q,k in bf16 (4MB each), v in fp32 (8MB)
__device__ __nv_bfloat16 g_qb[M_TOTAL * D_HEAD];
__device__ __nv_bfloat16 g_kb[M_TOTAL * D_HEAD];
__device__ float         g_v [M_TOTAL * D_HEAD];

__device__ __forceinline__ void cp16(void* dst, const void* src) {
    unsigned d = (unsigned)__cvta_generic_to_shared(dst);
    asm volatile("cp.async.cg.shared.global [%0], [%1], 16;\n" :: "r"(d), "l"(src));
}
#define CP_COMMIT() asm volatile("cp.async.commit_group;\n" ::: "memory")
#define CP_WAIT1()  asm volatile("cp.async.wait_group 1;\n" ::: "memory")

// ---------------------------------------------------------------------------
// Kernel 1: QKV projection (TF32). out[m,h] = sum_e x[m,e] W[h,e]
// q,k stored bf16 (q pre-scaled by QK_SCALE), v stored fp32.
// Block 256 thr, tile 64(M) x 128(N), K-chunks 32. grid (M/64, 3).
// Dynamic smem: 32KB (loads use 24KB; epilogue staging uses 32KB).
// ---------------------------------------------------------------------------
__global__ void __launch_bounds__(256) qkv_proj_kernel(
    const float* __restrict__ x,
    const float* __restrict__ Wq,
    const float* __restrict__ Wk,
    const float* __restrict__ Wv)
{
    extern __shared__ float psm[];
    float* As = psm;              // 64*32
    float* Bs = psm + 64 * 32;    // 128*32

    const int which = blockIdx.y;
    const float* W = (which == 0) ? Wq : (which == 1) ? Wk : Wv;

    const int row0 = blockIdx.x * 64;
    const int tid  = threadIdx.x;
    const int warp = tid >> 5;
    const int warpM = warp >> 1;
    const int warpN = warp & 1;

    wmma::fragment<wmma::accumulator, 16, 16, 8, float> acc[4];
    #pragma unroll
    for (int f = 0; f < 4; f++) wmma::fill_fragment(acc[f], 0.0f);

    for (int kc = 0; kc < D_EMBED; kc += 32) {
        #pragma unroll
        for (int i = 0; i < 2; i++) {
            int idx4 = tid + i * 256;
            int r = idx4 >> 3, c4 = idx4 & 7;
            ((float4*)As)[idx4] =
                *(const float4*)(x + (size_t)(row0 + r) * D_EMBED + kc + c4 * 4);
        }
        #pragma unroll
        for (int i = 0; i < 4; i++) {
            int idx4 = tid + i * 256;
            int r = idx4 >> 3, c4 = idx4 & 7;
            ((float4*)Bs)[idx4] =
                *(const float4*)(W + (size_t)r * D_EMBED + kc + c4 * 4);
        }
        __syncthreads();

        #pragma unroll
        for (int kk = 0; kk < 32; kk += 8) {
            wmma::fragment<wmma::matrix_a, 16, 16, 8, wmma::precision::tf32,
                           wmma::row_major> a;
            wmma::load_matrix_sync(a, As + warpM * 16 * 32 + kk, 32);
            #pragma unroll
            for (int t = 0; t < a.num_elements; t++)
                a.x[t] = wmma::__float_to_tf32(a.x[t]);
            #pragma unroll
            for (int f = 0; f < 4; f++) {
                wmma::fragment<wmma::matrix_b, 16, 16, 8, wmma::precision::tf32,
                               wmma::col_major> b;
                wmma::load_matrix_sync(b, Bs + (warpN * 64 + f * 16) * 32 + kk, 32);
                #pragma unroll
                for (int t = 0; t < b.num_elements; t++)
                    b.x[t] = wmma::__float_to_tf32(b.x[t]);
                wmma::mma_sync(acc[f], a, b, acc[f]);
            }
        }
        __syncthreads();
    }

    // Stage accumulators in smem (aliases As/Bs — safe after the sync above)
    float* stage = psm;  // 64*128 floats = 32KB
    #pragma unroll
    for (int f = 0; f < 4; f++)
        wmma::store_matrix_sync(stage + (warpM * 16) * 128 + warpN * 64 + f * 16,
                                acc[f], 128, wmma::mem_row_major);
    __syncthreads();

    if (which == 2) {
        float* vout = g_v + (size_t)row0 * D_HEAD;
        #pragma unroll
        for (int i = 0; i < 8; i++) {
            int idx4 = tid + i * 256;
            ((float4*)vout)[idx4] = ((float4*)stage)[idx4];
        }
    } else {
        __nv_bfloat16* outb = (which == 0) ? g_qb : g_kb;
        const float scl = (which == 0) ? QK_SCALE : 1.0f;
        __nv_bfloat162* ob2 = (__nv_bfloat162*)(outb + (size_t)row0 * D_HEAD);
        #pragma unroll
        for (int i = 0; i < 16; i++) {
            int idx2 = tid + i * 256;            // 0..4095 float2 pairs
            float2 t = ((float2*)stage)[idx2];
            ob2[idx2] = __floats2bfloat162_rn(t.x * scl, t.y * scl);
        }
    }
}

// ---------------------------------------------------------------------------
// Kernel 2: attention without online rescale.
//   O_unnorm += exp(S) @ V ;  l += rowsum(exp(S)) ;  out = O_unnorm / l
// Scores are O(0.01) by construction (scale 1/362), exp never overflows.
// Block = 64 q rows, 256 threads (8 warps as 4x2).
// smem: Kbf16[2] 2x16KB | Vf32[2] 2x32KB | Ss 16KB  = 112KB dynamic
// Q fragments + O accumulators live in registers for the whole loop.
// ---------------------------------------------------------------------------
#define ATTN_SMEM_BYTES (2*16384 + 2*32768 + 16384)

__global__ void __launch_bounds__(256) attn_kernel(float* __restrict__ out)
{
    extern __shared__ char sm[];
    __nv_bfloat16* Kb0 = (__nv_bfloat16*)sm;              // 16KB
    __nv_bfloat16* Kb1 = (__nv_bfloat16*)(sm + 16384);    // 16KB
    float* Vf0 = (float*)(sm + 32768);                    // 32KB
    float* Vf1 = (float*)(sm + 65536);                    // 32KB
    float* Ss  = (float*)(sm + 98304);                    // 16KB
    __nv_bfloat16* Qs = (__nv_bfloat16*)(sm + 98304);     // alias Ss (init only)
    float* stage = (float*)sm;                            // alias Kb/Vf (epilogue)
    __shared__ float l_s[64];

    const int tid  = threadIdx.x;
    const int warp = tid >> 5;
    const int warpM = warp >> 1;   // 0..3
    const int warpN = warp & 1;    // 0..1

    const int b  = blockIdx.x >> 6;
    const int qt = blockIdx.x & 63;

    const __nv_bfloat16* Qg  = g_qb + ((size_t)b * SEQ + qt * 64) * D_HEAD;
    const __nv_bfloat16* Kgb = g_kb + (size_t)b * SEQ * D_HEAD;
    const float*         Vgb = g_v  + (size_t)b * SEQ * D_HEAD;

    // --- init: stage Q (plain loads), prefetch tile 0 (cp.async) ---
    #pragma unroll
    for (int i = 0; i < 4; i++) {
        int c = tid + i * 256;                 // 1024 x 16B
        ((int4*)Qs)[c] = ((const int4*)Qg)[c];
    }
    #pragma unroll
    for (int i = 0; i < 4; i++) {
        int c = tid + i * 256;
        cp16(((int4*)Kb0) + c, ((const int4*)Kgb) + c);
    }
    #pragma unroll
    for (int i = 0; i < 8; i++) {
        int c = tid + i * 256;                 // 2048 x 16B
        cp16(((int4*)Vf0) + c, ((const int4*)Vgb) + c);
    }
    CP_COMMIT();
    if (tid < 64) l_s[tid] = 0.0f;
    __syncthreads();

    // --- Q fragments in registers (bf16, 8 k-chunks of 16) ---
    wmma::fragment<wmma::matrix_a, 16, 16, 16, __nv_bfloat16, wmma::row_major> qa[8];
    #pragma unroll
    for (int kk = 0; kk < 8; kk++)
        wmma::load_matrix_sync(qa[kk], Qs + warpM * 16 * 128 + kk * 16, 128);

    wmma::fragment<wmma::accumulator, 16, 16, 8, float> oacc[4];
    #pragma unroll
    for (int f = 0; f < 4; f++) wmma::fill_fragment(oacc[f], 0.0f);
    __syncthreads();   // Qs (= Ss) reusable now

    for (int kt = 0; kt < NT; kt++) {
        const int buf = kt & 1;
        __nv_bfloat16* Kcur = buf ? Kb1 : Kb0;
        __nv_bfloat16* Knxt = buf ? Kb0 : Kb1;
        float* Vcur = buf ? Vf1 : Vf0;
        float* Vnxt = buf ? Vf0 : Vf1;

        if (kt + 1 < NT) {
            const int4* ks = (const int4*)(Kgb + (size_t)(kt + 1) * 64 * D_HEAD);
            #pragma unroll
            for (int i = 0; i < 4; i++) {
                int c = tid + i * 256;
                cp16(((int4*)Knxt) + c, ks + c);
            }
            const int4* vs = (const int4*)(Vgb + (size_t)(kt + 1) * 64 * D_HEAD);
            #pragma unroll
            for (int i = 0; i < 8; i++) {
                int c = tid + i * 256;
                cp16(((int4*)Vnxt) + c, vs + c);
            }
        }
        CP_COMMIT();
        CP_WAIT1();          // tile kt resident
        __syncthreads();

        // ---- S = Q @ K^T (bf16 MMA, fp32 acc), warp tile 16x32 ----
        {
            wmma::fragment<wmma::accumulator, 16, 16, 16, float> sacc[2];
            #pragma unroll
            for (int f = 0; f < 2; f++) wmma::fill_fragment(sacc[f], 0.0f);
            #pragma unroll
            for (int kk = 0; kk < 8; kk++) {
                #pragma unroll
                for (int f = 0; f < 2; f++) {
                    wmma::fragment<wmma::matrix_b, 16, 16, 16, __nv_bfloat16,
                                   wmma::col_major> kb;
                    wmma::load_matrix_sync(kb,
                        Kcur + (warpN * 32 + f * 16) * 128 + kk * 16, 128);
                    wmma::mma_sync(sacc[f], qa[kk], kb, sacc[f]);
                }
            }
            #pragma unroll
            for (int f = 0; f < 2; f++)
                wmma::store_matrix_sync(Ss + warpM * 16 * 64 + warpN * 32 + f * 16,
                                        sacc[f], 64, wmma::mem_row_major);
        }
        __syncthreads();

        // ---- exp in place + row-sum accumulation (no max, no rescale) ----
        {
            const int r = tid >> 2;
            const int part = tid & 3;
            float* Srow = Ss + r * 64 + part * 16;
            float psum = 0.f;
            #pragma unroll
            for (int j = 0; j < 16; j++) {
                float p = __expf(Srow[j]);
                Srow[j] = p;
                psum += p;
            }
            psum += __shfl_xor_sync(0xffffffffu, psum, 1);
            psum += __shfl_xor_sync(0xffffffffu, psum, 2);
            if (part == 0) l_s[r] += psum;
        }
        __syncthreads();

        // ---- O += P @ V (TF32), warp tile 16x64, K=64 ----
        #pragma unroll
        for (int kk = 0; kk < 8; kk++) {
            wmma::fragment<wmma::matrix_a, 16, 16, 8, wmma::precision::tf32,
                           wmma::row_major> pa;
            wmma::load_matrix_sync(pa, Ss + warpM * 16 * 64 + kk * 8, 64);
            #pragma unroll
            for (int t = 0; t < pa.num_elements; t++)
                pa.x[t] = wmma::__float_to_tf32(pa.x[t]);
            #pragma unroll
            for (int f = 0; f < 4; f++) {
                wmma::fragment<wmma::matrix_b, 16, 16, 8, wmma::precision::tf32,
                               wmma::row_major> vb;
                wmma::load_matrix_sync(vb,
                    Vcur + kk * 8 * 128 + warpN * 64 + f * 16, 128);
                #pragma unroll
                for (int t = 0; t < vb.num_elements; t++)
                    vb.x[t] = wmma::__float_to_tf32(vb.x[t]);
                wmma::mma_sync(oacc[f], pa, vb, oacc[f]);
            }
        }
        __syncthreads();   // protect K/V/Ss before next iter's writes
    }

    // ---- epilogue: out = O_unnorm / l ----
    #pragma unroll
    for (int f = 0; f < 4; f++)
        wmma::store_matrix_sync(stage + warpM * 16 * 128 + warpN * 64 + f * 16,
                                oacc[f], 128, wmma::mem_row_major);
    __syncthreads();

    float* Og = out + ((size_t)b * SEQ + qt * 64) * D_HEAD;
    #pragma unroll
    for (int i = 0; i < 8; i++) {
        int idx4 = tid + i * 256;
        int r = idx4 >> 5;
        float inv = 1.0f / l_s[r];
        float4 t = ((float4*)stage)[idx4];
        t.x *= inv; t.y *= inv; t.z *= inv; t.w *= inv;
        ((float4*)Og)[idx4] = t;
    }
}

// ---------------------------------------------------------------------------
extern "C" void kernel_launch(void* const* d_in, const int* in_sizes, int n_in,
                              void* d_out, int out_size)
{
    const float* x  = (const float*)d_in[0];
    const float* Wq = (const float*)d_in[1];
    const float* Wk = (const float*)d_in[2];
    const float* Wv = (const float*)d_in[3];
    float* out = (float*)d_out;

    cudaFuncSetAttribute(attn_kernel,
                         cudaFuncAttributeMaxDynamicSharedMemorySize,
                         ATTN_SMEM_BYTES);

    dim3 gridProj(M_TOTAL / 64, 3);
    qkv_proj_kernel<<<gridProj, 256, 32 * 1024>>>(x, Wq, Wk, Wv);

    dim3 gridAttn(BATCH * (SEQ / 64));
    attn_kernel<<<gridAttn, 256, ATTN_SMEM_BYTES>>>(out);
}

// round 9
// speedup vs baseline: 2.0408x; 2.0408x over previous
#include <cuda_runtime.h>
#include <cuda_bf16.h>
#include <mma.h>

using namespace nvcuda;

#define D_EMBED 1024
#define D_HEAD  128
#define BATCH   4
#define SEQ     4096
#define M_TOTAL (BATCH * SEQ)
#define QK_SCALE (1.0f / 362.03867196751236f)
#define NT (SEQ / 64)

// Scratch: q,k bf16 (q pre-scaled), v fp32
__device__ __nv_bfloat16 g_qb[(size_t)M_TOTAL * D_HEAD];
__device__ __nv_bfloat16 g_kb[(size_t)M_TOTAL * D_HEAD];
__device__ float         g_v [(size_t)M_TOTAL * D_HEAD];

__device__ __forceinline__ void cp16(void* dst, const void* src) {
    unsigned d = (unsigned)__cvta_generic_to_shared(dst);
    asm volatile("cp.async.cg.shared.global [%0], [%1], 16;\n" :: "r"(d), "l"(src));
}
#define CP_COMMIT() asm volatile("cp.async.commit_group;\n" ::: "memory")
#define CP_WAIT1()  asm volatile("cp.async.wait_group 1;\n" ::: "memory")
#define CP_WAIT2()  asm volatile("cp.async.wait_group 2;\n" ::: "memory")

// ---------------------------------------------------------------------------
// Kernel 1: QKV projection (TF32 wmma), padded smem to kill bank conflicts.
// Block 256 thr, tile 64(M) x 128(N), K-chunks 32. grid (M/64, 3).
// As[64][36], Bs[128][36]; pad 36 -> 144B rows shift banks per row.
// ---------------------------------------------------------------------------
#define PJ_LDA 36
#define PJ_SMEM_BYTES (64 * 132 * 4)   // epilogue stage is the max user (33792)

__global__ void __launch_bounds__(256, 2) qkv_proj_kernel(
    const float* __restrict__ x,
    const float* __restrict__ Wq,
    const float* __restrict__ Wk,
    const float* __restrict__ Wv)
{
    extern __shared__ float psm[];
    float* As = psm;                    // 64*36
    float* Bs = psm + 64 * PJ_LDA;      // 128*36

    const int which = blockIdx.y;
    const float* W = (which == 0) ? Wq : (which == 1) ? Wk : Wv;

    const int row0 = blockIdx.x * 64;
    const int tid  = threadIdx.x;
    const int warp = tid >> 5;
    const int warpM = warp >> 1;
    const int warpN = warp & 1;

    wmma::fragment<wmma::accumulator, 16, 16, 8, float> acc[4];
    #pragma unroll
    for (int f = 0; f < 4; f++) wmma::fill_fragment(acc[f], 0.0f);

    for (int kc = 0; kc < D_EMBED; kc += 32) {
        #pragma unroll
        for (int i = 0; i < 2; i++) {
            int idx4 = tid + i * 256;           // 0..511 (64 rows x 8 chunks)
            int r = idx4 >> 3, c4 = idx4 & 7;
            *(float4*)(As + r * PJ_LDA + c4 * 4) =
                *(const float4*)(x + (size_t)(row0 + r) * D_EMBED + kc + c4 * 4);
        }
        #pragma unroll
        for (int i = 0; i < 4; i++) {
            int idx4 = tid + i * 256;           // 0..1023 (128 rows x 8)
            int r = idx4 >> 3, c4 = idx4 & 7;
            *(float4*)(Bs + r * PJ_LDA + c4 * 4) =
                *(const float4*)(W + (size_t)r * D_EMBED + kc + c4 * 4);
        }
        __syncthreads();

        #pragma unroll
        for (int kk = 0; kk < 32; kk += 8) {
            wmma::fragment<wmma::matrix_a, 16, 16, 8, wmma::precision::tf32,
                           wmma::row_major> a;
            wmma::load_matrix_sync(a, As + warpM * 16 * PJ_LDA + kk, PJ_LDA);
            #pragma unroll
            for (int t = 0; t < a.num_elements; t++)
                a.x[t] = wmma::__float_to_tf32(a.x[t]);
            #pragma unroll
            for (int f = 0; f < 4; f++) {
                wmma::fragment<wmma::matrix_b, 16, 16, 8, wmma::precision::tf32,
                               wmma::col_major> b;
                wmma::load_matrix_sync(b, Bs + (warpN * 64 + f * 16) * PJ_LDA + kk, PJ_LDA);
                #pragma unroll
                for (int t = 0; t < b.num_elements; t++)
                    b.x[t] = wmma::__float_to_tf32(b.x[t]);
                wmma::mma_sync(acc[f], a, b, acc[f]);
            }
        }
        __syncthreads();
    }

    // Epilogue via padded stage [64][132]
    float* stage = psm;
    #pragma unroll
    for (int f = 0; f < 4; f++)
        wmma::store_matrix_sync(stage + (warpM * 16) * 132 + warpN * 64 + f * 16,
                                acc[f], 132, wmma::mem_row_major);
    __syncthreads();

    if (which == 2) {
        float* vout = g_v + (size_t)row0 * D_HEAD;
        #pragma unroll
        for (int i = 0; i < 8; i++) {
            int idx4 = tid + i * 256;            // 64 rows x 32 float4
            int r = idx4 >> 5, c = idx4 & 31;
            ((float4*)vout)[idx4] = *(float4*)(stage + r * 132 + c * 4);
        }
    } else {
        __nv_bfloat16* outb = (which == 0) ? g_qb : g_kb;
        const float scl = (which == 0) ? QK_SCALE : 1.0f;
        __nv_bfloat162* ob2 = (__nv_bfloat162*)(outb + (size_t)row0 * D_HEAD);
        #pragma unroll
        for (int i = 0; i < 16; i++) {
            int idx2 = tid + i * 256;            // 64 rows x 64 float2
            int r = idx2 >> 6, c = idx2 & 63;
            float2 t = *(float2*)(stage + r * 132 + c * 2);
            ob2[idx2] = __floats2bfloat162_rn(t.x * scl, t.y * scl);
        }
    }
}

// ---------------------------------------------------------------------------
// Kernel 2: attention, no online rescale (scores O(0.01), exp can't overflow).
//   O += exp(S)@V ; l += rowsum(exp(S)) ; out = O/l
// Padded smem: K[2][64][136]bf16, V[64][132]f32, S/Q share [64][68]f32.
// K double-buffered; V prefetched per-iter (wait_group 2/1 split).
// MMA1 warps 4Mx2N (Q frags in regs); MMA2 warps 2Mx4N (halves V traffic).
// 86016 B smem/CTA -> 2 CTAs/SM.
// ---------------------------------------------------------------------------
#define AK_LD 136
#define AV_LD 132
#define AS_LD 68
#define OFF_K0 0
#define OFF_K1 17408
#define OFF_V  34816
#define OFF_S  68608
#define ATTN_SMEM_BYTES 86016

__global__ void __launch_bounds__(256, 2) attn_kernel(float* __restrict__ out)
{
    extern __shared__ char sm[];
    __nv_bfloat16* Kb0 = (__nv_bfloat16*)(sm + OFF_K0);
    __nv_bfloat16* Kb1 = (__nv_bfloat16*)(sm + OFF_K1);
    float*         Vs  = (float*)(sm + OFF_V);
    float*         Ss  = (float*)(sm + OFF_S);
    __nv_bfloat16* Qs  = (__nv_bfloat16*)(sm + OFF_S);   // alias (init only)
    float*         stage = (float*)sm;                   // alias (epilogue)
    __shared__ float l_s[64];

    const int tid  = threadIdx.x;
    const int warp = tid >> 5;
    const int wM1 = warp >> 1, wN1 = warp & 1;   // MMA1: 4M x 2N
    const int wM2 = warp & 1,  wN2 = warp >> 1;  // MMA2: 2M x 4N

    const int b  = blockIdx.x >> 6;
    const int qt = blockIdx.x & 63;

    const __nv_bfloat16* Qg  = g_qb + ((size_t)b * SEQ + qt * 64) * D_HEAD;
    const __nv_bfloat16* Kgb = g_kb + (size_t)b * SEQ * D_HEAD;
    const float*         Vgb = g_v  + (size_t)b * SEQ * D_HEAD;

    // K tile: 64 rows x 256B -> padded rows of 272B
    auto load_k = [&](int kt, __nv_bfloat16* buf) {
        const char* src = (const char*)(Kgb + (size_t)kt * 64 * D_HEAD);
        #pragma unroll
        for (int i = 0; i < 4; i++) {
            int idx = tid + i * 256;             // 0..1023
            int r = idx >> 4, c = idx & 15;
            cp16((char*)buf + r * (AK_LD * 2) + c * 16, src + r * 256 + c * 16);
        }
    };
    // V tile: 64 rows x 512B (fp32!) -> padded rows of 528B
    auto load_v = [&](int kt) {
        const char* src = (const char*)(Vgb + (size_t)kt * 64 * D_HEAD);
        #pragma unroll
        for (int i = 0; i < 8; i++) {
            int idx = tid + i * 256;             // 0..2047
            int r = idx >> 5, c = idx & 31;
            cp16((char*)Vs + r * (AV_LD * 4) + c * 16, src + r * 512 + c * 16);
        }
    };

    // Prologue: group {Q, K0}
    {
        const char* qsrc = (const char*)Qg;
        #pragma unroll
        for (int i = 0; i < 4; i++) {
            int idx = tid + i * 256;
            int r = idx >> 4, c = idx & 15;
            cp16((char*)Qs + r * (AK_LD * 2) + c * 16, qsrc + r * 256 + c * 16);
        }
        load_k(0, Kb0);
        CP_COMMIT();
    }
    if (tid < 64) l_s[tid] = 0.0f;

    wmma::fragment<wmma::matrix_a, 16, 16, 16, __nv_bfloat16, wmma::row_major> qa[8];
    wmma::fragment<wmma::accumulator, 16, 16, 8, float> oacc[4];
    #pragma unroll
    for (int f = 0; f < 4; f++) wmma::fill_fragment(oacc[f], 0.0f);

    bool qloaded = false;

    for (int kt = 0; kt < NT; kt++) {
        __nv_bfloat16* Kcur = (kt & 1) ? Kb1 : Kb0;
        __nv_bfloat16* Knxt = (kt & 1) ? Kb0 : Kb1;

        load_v(kt);  CP_COMMIT();                  // group V(kt)
        if (kt + 1 < NT) load_k(kt + 1, Knxt);     // guarded: no writes in flight
        CP_COMMIT();                               // group K(kt+1) (possibly empty)

        CP_WAIT2();                                // K(kt) (and older) resident
        __syncthreads();

        if (!qloaded) {   // Q arrived with K0; pull fragments, then free Qs(=Ss)
            #pragma unroll
            for (int kk = 0; kk < 8; kk++)
                wmma::load_matrix_sync(qa[kk], Qs + wM1 * 16 * AK_LD + kk * 16, AK_LD);
            qloaded = true;
            __syncthreads();
        }

        // ---- MMA1: S = Q @ K^T (bf16), warps 4M x 2N ----
        {
            wmma::fragment<wmma::accumulator, 16, 16, 16, float> sacc[2];
            #pragma unroll
            for (int f = 0; f < 2; f++) wmma::fill_fragment(sacc[f], 0.0f);
            #pragma unroll
            for (int kk = 0; kk < 8; kk++) {
                #pragma unroll
                for (int f = 0; f < 2; f++) {
                    wmma::fragment<wmma::matrix_b, 16, 16, 16, __nv_bfloat16,
                                   wmma::col_major> kb;
                    wmma::load_matrix_sync(kb,
                        Kcur + (wN1 * 32 + f * 16) * AK_LD + kk * 16, AK_LD);
                    wmma::mma_sync(sacc[f], qa[kk], kb, sacc[f]);
                }
            }
            #pragma unroll
            for (int f = 0; f < 2; f++)
                wmma::store_matrix_sync(Ss + wM1 * 16 * AS_LD + wN1 * 32 + f * 16,
                                        sacc[f], AS_LD, wmma::mem_row_major);
        }
        __syncthreads();

        // ---- exp in place + row-sum ----
        {
            const int r = tid >> 2;
            const int part = tid & 3;
            float* Srow = Ss + r * AS_LD + part * 16;
            float psum = 0.f;
            #pragma unroll
            for (int j = 0; j < 16; j++) {
                float p = __expf(Srow[j]);
                Srow[j] = p;
                psum += p;
            }
            psum += __shfl_xor_sync(0xffffffffu, psum, 1);
            psum += __shfl_xor_sync(0xffffffffu, psum, 2);
            if (part == 0) l_s[r] += psum;
        }
        CP_WAIT1();                                // V(kt) resident (K(kt+1) may fly)
        __syncthreads();

        // ---- MMA2: O += P @ V (TF32), warps 2M x 4N ----
        #pragma unroll
        for (int kk = 0; kk < 8; kk++) {
            wmma::fragment<wmma::matrix_a, 16, 16, 8, wmma::precision::tf32,
                           wmma::row_major> pa[2];
            #pragma unroll
            for (int mf = 0; mf < 2; mf++) {
                wmma::load_matrix_sync(pa[mf],
                    Ss + (wM2 * 32 + mf * 16) * AS_LD + kk * 8, AS_LD);
                #pragma unroll
                for (int t = 0; t < pa[mf].num_elements; t++)
                    pa[mf].x[t] = wmma::__float_to_tf32(pa[mf].x[t]);
            }
            #pragma unroll
            for (int nf = 0; nf < 2; nf++) {
                wmma::fragment<wmma::matrix_b, 16, 16, 8, wmma::precision::tf32,
                               wmma::row_major> vb;
                wmma::load_matrix_sync(vb,
                    Vs + kk * 8 * AV_LD + wN2 * 32 + nf * 16, AV_LD);
                #pragma unroll
                for (int t = 0; t < vb.num_elements; t++)
                    vb.x[t] = wmma::__float_to_tf32(vb.x[t]);
                #pragma unroll
                for (int mf = 0; mf < 2; mf++)
                    wmma::mma_sync(oacc[mf * 2 + nf], pa[mf], vb, oacc[mf * 2 + nf]);
            }
        }
        __syncthreads();   // V/S consumed before next iter overwrites
    }

    // ---- epilogue: out = O / l  (no cp.async writes in flight now) ----
    #pragma unroll
    for (int mf = 0; mf < 2; mf++)
        #pragma unroll
        for (int nf = 0; nf < 2; nf++)
            wmma::store_matrix_sync(
                stage + (wM2 * 32 + mf * 16) * AV_LD + wN2 * 32 + nf * 16,
                oacc[mf * 2 + nf], AV_LD, wmma::mem_row_major);
    __syncthreads();

    float* Og = out + ((size_t)b * SEQ + qt * 64) * D_HEAD;
    #pragma unroll
    for (int i = 0; i < 8; i++) {
        int idx4 = tid + i * 256;
        int r = idx4 >> 5, c = idx4 & 31;
        float inv = 1.0f / l_s[r];
        float4 t = *(float4*)(stage + r * AV_LD + c * 4);
        t.x *= inv; t.y *= inv; t.z *= inv; t.w *= inv;
        ((float4*)Og)[idx4] = t;
    }
}

// ---------------------------------------------------------------------------
extern "C" void kernel_launch(void* const* d_in, const int* in_sizes, int n_in,
                              void* d_out, int out_size)
{
    const float* x  = (const float*)d_in[0];
    const float* Wq = (const float*)d_in[1];
    const float* Wk = (const float*)d_in[2];
    const float* Wv = (const float*)d_in[3];
    float* out = (float*)d_out;

    cudaFuncSetAttribute(qkv_proj_kernel,
                         cudaFuncAttributeMaxDynamicSharedMemorySize, PJ_SMEM_BYTES);
    cudaFuncSetAttribute(attn_kernel,
                         cudaFuncAttributeMaxDynamicSharedMemorySize, ATTN_SMEM_BYTES);

    dim3 gridProj(M_TOTAL / 64, 3);
    qkv_proj_kernel<<<gridProj, 256, PJ_SMEM_BYTES>>>(x, Wq, Wk, Wv);

    dim3 gridAttn(BATCH * (SEQ / 64));
    attn_kernel<<<gridAttn, 256, ATTN_SMEM_BYTES>>>(out);
}

// round 13
// speedup vs baseline: 3.6038x; 1.7658x over previous
#include <cuda_runtime.h>
#include <cuda_bf16.h>
#include <mma.h>
#include <cstdint>

using namespace nvcuda;

#define D_EMBED 1024
#define D_HEAD  128
#define BATCH   4
#define SEQ     4096
#define M_TOTAL (BATCH * SEQ)
#define QK_SCALE (1.0f / 362.03867196751236f)
#define NT (SEQ / 64)

// Scratch
__device__ __nv_bfloat16 g_qb [(size_t)M_TOTAL * D_HEAD];   // q bf16 (pre-scaled)
__device__ __nv_bfloat16 g_kb [(size_t)M_TOTAL * D_HEAD];   // k bf16
__device__ __nv_bfloat16 g_vb [(size_t)M_TOTAL * D_HEAD];   // v bf16
__device__ float         g_vpart[(M_TOTAL / 64) * D_HEAD];  // per-64-row-tile column sums of v (f32)
__device__ __nv_bfloat16 g_xb [(size_t)M_TOTAL * D_EMBED];  // x bf16
__device__ __nv_bfloat16 g_wqb[(size_t)D_HEAD * D_EMBED];
__device__ __nv_bfloat16 g_wkb[(size_t)D_HEAD * D_EMBED];

__device__ __forceinline__ void cp16(void* dst, const void* src) {
    unsigned d = (unsigned)__cvta_generic_to_shared(dst);
    asm volatile("cp.async.cg.shared.global [%0], [%1], 16;\n" :: "r"(d), "l"(src));
}
#define CP_COMMIT() asm volatile("cp.async.commit_group;\n" ::: "memory")
#define CP_WAIT0()  asm volatile("cp.async.wait_group 0;\n" ::: "memory")
#define CP_WAIT1()  asm volatile("cp.async.wait_group 1;\n" ::: "memory")
#define CP_WAIT2()  asm volatile("cp.async.wait_group 2;\n" ::: "memory")

// ---------------------------------------------------------------------------
// Kernel 0: convert x, Wq, Wk to bf16 (feeds the bf16 q/k projections).
// ---------------------------------------------------------------------------
__global__ void __launch_bounds__(256) round_kernel(
    const float* __restrict__ x,
    const float* __restrict__ wq,
    const float* __restrict__ wk)
{
    const size_t nx2 = (size_t)M_TOTAL * D_EMBED / 2;
    const size_t nw2 = (size_t)D_HEAD * D_EMBED / 2;
    const size_t stride = (size_t)gridDim.x * blockDim.x;
    const size_t t0 = (size_t)blockIdx.x * blockDim.x + threadIdx.x;

    const float2* x2 = (const float2*)x;
    __nv_bfloat162* xb2 = (__nv_bfloat162*)g_xb;
    for (size_t i = t0; i < nx2; i += stride) {
        float2 t = x2[i];
        xb2[i] = __floats2bfloat162_rn(t.x, t.y);
    }
    const float2* q2 = (const float2*)wq;
    const float2* k2 = (const float2*)wk;
    __nv_bfloat162* qb2 = (__nv_bfloat162*)g_wqb;
    __nv_bfloat162* kb2 = (__nv_bfloat162*)g_wkb;
    for (size_t i = t0; i < nw2; i += stride) {
        float2 a = q2[i]; qb2[i] = __floats2bfloat162_rn(a.x, a.y);
        float2 b = k2[i]; kb2[i] = __floats2bfloat162_rn(b.x, b.y);
    }
}

// ---------------------------------------------------------------------------
// Kernel 1: q/k projection in bf16 (error contribution ~2e-5; see analysis).
// Block 256 thr, tile 64(M) x 128(N), K-chunks of 64 bf16, double-buffered.
// As[64][72] Bs[128][72] bf16 (144B rows: 16B-aligned, bank-shifting).
// ---------------------------------------------------------------------------
#define QK_LD 72
#define QK_ABUF (64 * QK_LD * 2)        // 9216
#define QK_BBUF (128 * QK_LD * 2)       // 18432
#define QK_BUF  (QK_ABUF + QK_BBUF)     // 27648
#define QK_SMEM_BYTES (2 * QK_BUF)      // 55296 (stage 33792 aliases)

__global__ void __launch_bounds__(256, 2) proj_qk_kernel()
{
    extern __shared__ char sm[];
    const int which = blockIdx.y;                 // 0 = q, 1 = k
    const __nv_bfloat16* X = g_xb;
    const __nv_bfloat16* W = which ? g_wkb : g_wqb;

    const int row0 = blockIdx.x * 64;
    const int tid  = threadIdx.x;
    const int warp = tid >> 5;
    const int warpM = warp >> 1;
    const int warpN = warp & 1;

    auto load_chunk = [&](int c) {
        char* As = sm + (c & 1) * QK_BUF;
        char* Bs = As + QK_ABUF;
        #pragma unroll
        for (int i = 0; i < 2; i++) {             // A: 64 rows x 8 16B chunks
            int idx = tid + i * 256;
            int r = idx >> 3, cb = (idx & 7) << 4;
            cp16(As + r * 144 + cb,
                 (const char*)(X + (size_t)(row0 + r) * D_EMBED + c * 64) + cb);
        }
        #pragma unroll
        for (int i = 0; i < 4; i++) {             // B: 128 rows x 8
            int idx = tid + i * 256;
            int r = idx >> 3, cb = (idx & 7) << 4;
            cp16(Bs + r * 144 + cb,
                 (const char*)(W + (size_t)r * D_EMBED + c * 64) + cb);
        }
        CP_COMMIT();
    };

    wmma::fragment<wmma::accumulator, 16, 16, 16, float> acc[4];
    #pragma unroll
    for (int f = 0; f < 4; f++) wmma::fill_fragment(acc[f], 0.0f);

    load_chunk(0);
    for (int c = 0; c < 16; c++) {
        if (c + 1 < 16) { load_chunk(c + 1); CP_WAIT1(); } else { CP_WAIT0(); }
        __syncthreads();
        __nv_bfloat16* As = (__nv_bfloat16*)(sm + (c & 1) * QK_BUF);
        __nv_bfloat16* Bs = (__nv_bfloat16*)((char*)As + QK_ABUF);
        #pragma unroll
        for (int kk = 0; kk < 4; kk++) {
            wmma::fragment<wmma::matrix_a, 16, 16, 16, __nv_bfloat16,
                           wmma::row_major> a;
            wmma::load_matrix_sync(a, As + warpM * 16 * QK_LD + kk * 16, QK_LD);
            #pragma unroll
            for (int f = 0; f < 4; f++) {
                wmma::fragment<wmma::matrix_b, 16, 16, 16, __nv_bfloat16,
                               wmma::col_major> b;
                wmma::load_matrix_sync(b, Bs + (warpN * 64 + f * 16) * QK_LD + kk * 16, QK_LD);
                wmma::mma_sync(acc[f], a, b, acc[f]);
            }
        }
        __syncthreads();
    }

    float* stage = (float*)sm;                    // [64][132]
    #pragma unroll
    for (int f = 0; f < 4; f++)
        wmma::store_matrix_sync(stage + warpM * 16 * 132 + warpN * 64 + f * 16,
                                acc[f], 132, wmma::mem_row_major);
    __syncthreads();

    __nv_bfloat16* outb = which ? g_kb : g_qb;
    const float scl = which ? 1.0f : (float)QK_SCALE;
    __nv_bfloat162* ob2 = (__nv_bfloat162*)(outb + (size_t)row0 * D_HEAD);
    #pragma unroll
    for (int i = 0; i < 16; i++) {
        int idx2 = tid + i * 256;                 // 64 rows x 64 pairs
        int r = idx2 >> 6, cc = idx2 & 63;
        float2 t = *(float2*)(stage + r * 132 + cc * 2);
        ob2[idx2] = __floats2bfloat162_rn(t.x * scl, t.y * scl);
    }
}

// ---------------------------------------------------------------------------
// Kernel 2: v projection (TF32 — v accuracy dominates final error).
// Same structure as round-9 proj; epilogue writes v as bf16 + f32 column sums.
// ---------------------------------------------------------------------------
#define PJ_LDA 36
#define PJ_SMEM_BYTES (64 * 132 * 4)

__global__ void __launch_bounds__(256, 2) proj_v_kernel(
    const float* __restrict__ x, const float* __restrict__ Wv)
{
    extern __shared__ float psm[];
    float* As = psm;
    float* Bs = psm + 64 * PJ_LDA;
    __shared__ float cpart[2][128];

    const int row0 = blockIdx.x * 64;
    const int tid  = threadIdx.x;
    const int warp = tid >> 5;
    const int warpM = warp >> 1;
    const int warpN = warp & 1;

    wmma::fragment<wmma::accumulator, 16, 16, 8, float> acc[4];
    #pragma unroll
    for (int f = 0; f < 4; f++) wmma::fill_fragment(acc[f], 0.0f);

    for (int kc = 0; kc < D_EMBED; kc += 32) {
        #pragma unroll
        for (int i = 0; i < 2; i++) {
            int idx4 = tid + i * 256;
            int r = idx4 >> 3, c4 = idx4 & 7;
            *(float4*)(As + r * PJ_LDA + c4 * 4) =
                *(const float4*)(x + (size_t)(row0 + r) * D_EMBED + kc + c4 * 4);
        }
        #pragma unroll
        for (int i = 0; i < 4; i++) {
            int idx4 = tid + i * 256;
            int r = idx4 >> 3, c4 = idx4 & 7;
            *(float4*)(Bs + r * PJ_LDA + c4 * 4) =
                *(const float4*)(Wv + (size_t)r * D_EMBED + kc + c4 * 4);
        }
        __syncthreads();

        #pragma unroll
        for (int kk = 0; kk < 32; kk += 8) {
            wmma::fragment<wmma::matrix_a, 16, 16, 8, wmma::precision::tf32,
                           wmma::row_major> a;
            wmma::load_matrix_sync(a, As + warpM * 16 * PJ_LDA + kk, PJ_LDA);
            #pragma unroll
            for (int t = 0; t < a.num_elements; t++)
                a.x[t] = wmma::__float_to_tf32(a.x[t]);
            #pragma unroll
            for (int f = 0; f < 4; f++) {
                wmma::fragment<wmma::matrix_b, 16, 16, 8, wmma::precision::tf32,
                               wmma::col_major> b;
                wmma::load_matrix_sync(b, Bs + (warpN * 64 + f * 16) * PJ_LDA + kk, PJ_LDA);
                #pragma unroll
                for (int t = 0; t < b.num_elements; t++)
                    b.x[t] = wmma::__float_to_tf32(b.x[t]);
                wmma::mma_sync(acc[f], a, b, acc[f]);
            }
        }
        __syncthreads();
    }

    float* stage = psm;                           // [64][132]
    #pragma unroll
    for (int f = 0; f < 4; f++)
        wmma::store_matrix_sync(stage + warpM * 16 * 132 + warpN * 64 + f * 16,
                                acc[f], 132, wmma::mem_row_major);
    __syncthreads();

    // v -> bf16
    __nv_bfloat162* ob2 = (__nv_bfloat162*)(g_vb + (size_t)row0 * D_HEAD);
    #pragma unroll
    for (int i = 0; i < 16; i++) {
        int idx2 = tid + i * 256;
        int r = idx2 >> 6, cc = idx2 & 63;
        float2 t = *(float2*)(stage + r * 132 + cc * 2);
        ob2[idx2] = __floats2bfloat162_rn(t.x, t.y);
    }
    // exact f32 column sums of this 64-row tile (deterministic)
    {
        const int c = tid & 127, half = tid >> 7;
        float s = 0.f;
        #pragma unroll
        for (int r = 0; r < 32; r++) s += stage[(half * 32 + r) * 132 + c];
        cpart[half][c] = s;
    }
    __syncthreads();
    if (tid < 128)
        g_vpart[blockIdx.x * 128 + tid] = cpart[0][tid] + cpart[1][tid];
}

// ---------------------------------------------------------------------------
// Kernel 3: attention via the P-1 decomposition — all bf16 MMAs.
//   O = (Vsum + sum_k (exp(s)-1) * v_bf16) / (4096 + sum(exp(s)-1))
// smem: K[2][64][136]bf16 | V[64][136]bf16 | P'[64][72]bf16 | S[64][68]f32
// Q staged in K1 pre-loop; epilogue stage aliases K0+K1.
// ---------------------------------------------------------------------------
#define AK_LD 136
#define AP_LD 72
#define AS_LD 68
#define OFF_K0 0
#define OFF_K1 17408
#define OFF_V  34816
#define OFF_P  52224
#define OFF_S  61440
#define ATTN_SMEM_BYTES (OFF_S + 64 * AS_LD * 4)   // 78848

__global__ void __launch_bounds__(256, 2) attn_kernel(float* __restrict__ out)
{
    extern __shared__ char sm[];
    __nv_bfloat16* Kb0 = (__nv_bfloat16*)(sm + OFF_K0);
    __nv_bfloat16* Kb1 = (__nv_bfloat16*)(sm + OFF_K1);
    __nv_bfloat16* Vb  = (__nv_bfloat16*)(sm + OFF_V);
    __nv_bfloat16* Ps  = (__nv_bfloat16*)(sm + OFF_P);
    float*         Ss  = (float*)(sm + OFF_S);
    float*         stage = (float*)sm;            // epilogue alias (K0+K1)
    __shared__ float l_s[64];
    __shared__ float vsum_s[128];

    const int tid  = threadIdx.x;
    const int warp = tid >> 5;
    const int wM1 = warp >> 1, wN1 = warp & 1;    // MMA1: 4M x 2N
    const int wM2 = warp & 1,  wN2 = warp >> 1;   // MMA2: 2M x 4N

    const int b  = blockIdx.x >> 6;
    const int qt = blockIdx.x & 63;

    const __nv_bfloat16* Qg  = g_qb + ((size_t)b * SEQ + qt * 64) * D_HEAD;
    const __nv_bfloat16* Kgb = g_kb + (size_t)b * SEQ * D_HEAD;
    const __nv_bfloat16* Vgb = g_vb + (size_t)b * SEQ * D_HEAD;

    // 64 rows x 256B (bf16) -> padded rows of 272B (16B aligned)
    auto load_tile = [&](const __nv_bfloat16* src0, void* buf) {
        const char* src = (const char*)src0;
        #pragma unroll
        for (int i = 0; i < 4; i++) {
            int idx = tid + i * 256;              // 0..1023
            int r = idx >> 4, c = idx & 15;
            cp16((char*)buf + r * 272 + c * 16, src + r * 256 + c * 16);
        }
    };

    // Prologue: {Q -> Kb1, K0 -> Kb0} in one group
    load_tile(Qg, Kb1);
    load_tile(Kgb, Kb0);
    CP_COMMIT();

    // Vsum for this batch (exact f32 from proj partials)
    if (tid < 128) {
        float s = 0.f;
        #pragma unroll 8
        for (int i = 0; i < 64; i++) s += g_vpart[(b * 64 + i) * 128 + tid];
        vsum_s[tid] = s;
    }
    if (tid < 64) l_s[tid] = 0.0f;

    CP_WAIT0();
    __syncthreads();

    wmma::fragment<wmma::matrix_a, 16, 16, 16, __nv_bfloat16, wmma::row_major> qa[8];
    #pragma unroll
    for (int kk = 0; kk < 8; kk++)
        wmma::load_matrix_sync(qa[kk], Kb1 + wM1 * 16 * AK_LD + kk * 16, AK_LD);
    __syncthreads();                               // Kb1 free for K(1)

    wmma::fragment<wmma::accumulator, 16, 16, 16, float> oacc[4];
    #pragma unroll
    for (int f = 0; f < 4; f++) wmma::fill_fragment(oacc[f], 0.0f);

    for (int kt = 0; kt < NT; kt++) {
        __nv_bfloat16* Kcur = (kt & 1) ? Kb1 : Kb0;
        __nv_bfloat16* Knxt = (kt & 1) ? Kb0 : Kb1;

        load_tile(Vgb + (size_t)kt * 64 * D_HEAD, Vb);  CP_COMMIT();   // {V(kt)}
        if (kt + 1 < NT) load_tile(Kgb + (size_t)(kt + 1) * 64 * D_HEAD, Knxt);
        CP_COMMIT();                                                   // {K(kt+1)}

        CP_WAIT2();                                // K(kt) and older resident
        __syncthreads();

        // ---- MMA1: S = Q @ K^T (bf16) ----
        {
            wmma::fragment<wmma::accumulator, 16, 16, 16, float> sacc[2];
            #pragma unroll
            for (int f = 0; f < 2; f++) wmma::fill_fragment(sacc[f], 0.0f);
            #pragma unroll
            for (int kk = 0; kk < 8; kk++) {
                #pragma unroll
                for (int f = 0; f < 2; f++) {
                    wmma::fragment<wmma::matrix_b, 16, 16, 16, __nv_bfloat16,
                                   wmma::col_major> kb;
                    wmma::load_matrix_sync(kb,
                        Kcur + (wN1 * 32 + f * 16) * AK_LD + kk * 16, AK_LD);
                    wmma::mma_sync(sacc[f], qa[kk], kb, sacc[f]);
                }
            }
            #pragma unroll
            for (int f = 0; f < 2; f++)
                wmma::store_matrix_sync(Ss + wM1 * 16 * AS_LD + wN1 * 32 + f * 16,
                                        sacc[f], AS_LD, wmma::mem_row_major);
        }
        __syncthreads();

        // ---- P' = exp(S) - 1 (f32 -> bf16), row sums in f32 ----
        {
            const int r = tid >> 2;
            const int part = tid & 3;
            const float* Srow = Ss + r * AS_LD + part * 16;
            __nv_bfloat162* Prow = (__nv_bfloat162*)(Ps + r * AP_LD + part * 16);
            float psum = 0.f;
            #pragma unroll
            for (int j = 0; j < 16; j += 2) {
                float p0 = __expf(Srow[j])     - 1.0f;
                float p1 = __expf(Srow[j + 1]) - 1.0f;
                psum += p0 + p1;
                Prow[j >> 1] = __floats2bfloat162_rn(p0, p1);
            }
            psum += __shfl_xor_sync(0xffffffffu, psum, 1);
            psum += __shfl_xor_sync(0xffffffffu, psum, 2);
            if (part == 0) l_s[r] += psum;
        }
        CP_WAIT1();                                // V(kt) resident
        __syncthreads();

        // ---- MMA2: O' += P' @ V (bf16), warps 2M x 4N ----
        #pragma unroll
        for (int kk = 0; kk < 4; kk++) {
            wmma::fragment<wmma::matrix_a, 16, 16, 16, __nv_bfloat16,
                           wmma::row_major> pa[2];
            #pragma unroll
            for (int mf = 0; mf < 2; mf++)
                wmma::load_matrix_sync(pa[mf],
                    Ps + (wM2 * 32 + mf * 16) * AP_LD + kk * 16, AP_LD);
            #pragma unroll
            for (int nf = 0; nf < 2; nf++) {
                wmma::fragment<wmma::matrix_b, 16, 16, 16, __nv_bfloat16,
                               wmma::row_major> vb;
                wmma::load_matrix_sync(vb,
                    Vb + kk * 16 * AK_LD + wN2 * 32 + nf * 16, AK_LD);
                #pragma unroll
                for (int mf = 0; mf < 2; mf++)
                    wmma::mma_sync(oacc[mf * 2 + nf], pa[mf], vb, oacc[mf * 2 + nf]);
            }
        }
        __syncthreads();
    }

    // ---- epilogue: out = (vsum + O') / (4096 + l) ----
    #pragma unroll
    for (int mf = 0; mf < 2; mf++)
        #pragma unroll
        for (int nf = 0; nf < 2; nf++)
            wmma::store_matrix_sync(
                stage + (wM2 * 32 + mf * 16) * 132 + wN2 * 32 + nf * 16,
                oacc[mf * 2 + nf], 132, wmma::mem_row_major);
    __syncthreads();

    float* Og = out + ((size_t)b * SEQ + qt * 64) * D_HEAD;
    #pragma unroll
    for (int i = 0; i < 8; i++) {
        int idx4 = tid + i * 256;
        int r = idx4 >> 5, c = idx4 & 31;
        float inv = 1.0f / (4096.0f + l_s[r]);
        float4 t = *(float4*)(stage + r * 132 + c * 4);
        t.x = (t.x + vsum_s[c * 4 + 0]) * inv;
        t.y = (t.y + vsum_s[c * 4 + 1]) * inv;
        t.z = (t.z + vsum_s[c * 4 + 2]) * inv;
        t.w = (t.w + vsum_s[c * 4 + 3]) * inv;
        ((float4*)Og)[idx4] = t;
    }
}

// ---------------------------------------------------------------------------
extern "C" void kernel_launch(void* const* d_in, const int* in_sizes, int n_in,
                              void* d_out, int out_size)
{
    const float* x  = (const float*)d_in[0];
    const float* Wq = (const float*)d_in[1];
    const float* Wk = (const float*)d_in[2];
    const float* Wv = (const float*)d_in[3];
    float* out = (float*)d_out;

    cudaFuncSetAttribute(proj_qk_kernel,
                         cudaFuncAttributeMaxDynamicSharedMemorySize, QK_SMEM_BYTES);
    cudaFuncSetAttribute(proj_v_kernel,
                         cudaFuncAttributeMaxDynamicSharedMemorySize, PJ_SMEM_BYTES);
    cudaFuncSetAttribute(attn_kernel,
                         cudaFuncAttributeMaxDynamicSharedMemorySize, ATTN_SMEM_BYTES);

    round_kernel<<<512, 256>>>(x, Wq, Wk);

    dim3 gridQK(M_TOTAL / 64, 2);
    proj_qk_kernel<<<gridQK, 256, QK_SMEM_BYTES>>>();

    proj_v_kernel<<<M_TOTAL / 64, 256, PJ_SMEM_BYTES>>>(x, Wv);

    attn_kernel<<<BATCH * (SEQ / 64), 256, ATTN_SMEM_BYTES>>>(out);
}

// round 14
// speedup vs baseline: 5.0363x; 1.3975x over previous
#include <cuda_runtime.h>
#include <cuda_bf16.h>
#include <mma.h>
#include <cstdint>

using namespace nvcuda;

#define D_EMBED 1024
#define D_HEAD  128
#define BATCH   4
#define SEQ     4096
#define M_TOTAL (BATCH * SEQ)
#define QK_SCALE (1.0f / 362.03867196751236f)
#define NT (SEQ / 64)

// Scratch
__device__ __nv_bfloat16 g_qb [(size_t)M_TOTAL * D_HEAD];   // q bf16 (pre-scaled)
__device__ __nv_bfloat16 g_kb [(size_t)M_TOTAL * D_HEAD];   // k bf16
__device__ __nv_bfloat16 g_vb [(size_t)M_TOTAL * D_HEAD];   // v bf16
__device__ float         g_vpart[(M_TOTAL / 64) * D_HEAD];  // per-64-row-tile column sums of v
__device__ __nv_bfloat16 g_xb [(size_t)M_TOTAL * D_EMBED];  // x bf16
__device__ __nv_bfloat16 g_wqb[(size_t)D_HEAD * D_EMBED];
__device__ __nv_bfloat16 g_wkb[(size_t)D_HEAD * D_EMBED];

__device__ __forceinline__ uint32_t smem_u32(const void* p) {
    uint32_t a;
    asm("{ .reg .u64 t; cvta.to.shared.u64 t, %1; cvt.u32.u64 %0, t; }" : "=r"(a) : "l"(p));
    return a;
}
__device__ __forceinline__ void cp16(uint32_t dst, const void* src) {
    asm volatile("cp.async.cg.shared.global [%0], [%1], 16;\n" :: "r"(dst), "l"(src));
}
__device__ __forceinline__ void cp16p(void* dst, const void* src) {
    unsigned d = (unsigned)__cvta_generic_to_shared(dst);
    asm volatile("cp.async.cg.shared.global [%0], [%1], 16;\n" :: "r"(d), "l"(src));
}
#define CP_COMMIT() asm volatile("cp.async.commit_group;\n" ::: "memory")
#define CP_WAIT0()  asm volatile("cp.async.wait_group 0;\n" ::: "memory")
#define CP_WAIT1()  asm volatile("cp.async.wait_group 1;\n" ::: "memory")

#define LDSM4(r0, r1, r2, r3, a) \
    asm volatile("ldmatrix.sync.aligned.m8n8.x4.shared.b16 {%0,%1,%2,%3}, [%4];" \
        : "=r"(r0), "=r"(r1), "=r"(r2), "=r"(r3) : "r"(a))
#define LDSM4T(r0, r1, r2, r3, a) \
    asm volatile("ldmatrix.sync.aligned.m8n8.x4.trans.shared.b16 {%0,%1,%2,%3}, [%4];" \
        : "=r"(r0), "=r"(r1), "=r"(r2), "=r"(r3) : "r"(a))
#define MMA16816(c, a, b0, b1) \
    asm volatile("mma.sync.aligned.m16n8k16.row.col.f32.bf16.bf16.f32 " \
        "{%0,%1,%2,%3},{%4,%5,%6,%7},{%8,%9},{%0,%1,%2,%3};" \
        : "+f"((c)[0]), "+f"((c)[1]), "+f"((c)[2]), "+f"((c)[3]) \
        : "r"((a)[0]), "r"((a)[1]), "r"((a)[2]), "r"((a)[3]), "r"(b0), "r"(b1))

__device__ __forceinline__ uint32_t packbf(float x, float y) {
    __nv_bfloat162 t = __floats2bfloat162_rn(x, y);
    return *reinterpret_cast<uint32_t*>(&t);
}

// ---------------------------------------------------------------------------
// Kernel 0: convert x, Wq, Wk to bf16
// ---------------------------------------------------------------------------
__global__ void __launch_bounds__(256) round_kernel(
    const float* __restrict__ x,
    const float* __restrict__ wq,
    const float* __restrict__ wk)
{
    const size_t nx2 = (size_t)M_TOTAL * D_EMBED / 2;
    const size_t nw2 = (size_t)D_HEAD * D_EMBED / 2;
    const size_t stride = (size_t)gridDim.x * blockDim.x;
    const size_t t0 = (size_t)blockIdx.x * blockDim.x + threadIdx.x;

    const float2* x2 = (const float2*)x;
    __nv_bfloat162* xb2 = (__nv_bfloat162*)g_xb;
    for (size_t i = t0; i < nx2; i += stride) {
        float2 t = x2[i];
        xb2[i] = __floats2bfloat162_rn(t.x, t.y);
    }
    const float2* q2 = (const float2*)wq;
    const float2* k2 = (const float2*)wk;
    __nv_bfloat162* qb2 = (__nv_bfloat162*)g_wqb;
    __nv_bfloat162* kb2 = (__nv_bfloat162*)g_wkb;
    for (size_t i = t0; i < nw2; i += stride) {
        float2 a = q2[i]; qb2[i] = __floats2bfloat162_rn(a.x, a.y);
        float2 b = k2[i]; kb2[i] = __floats2bfloat162_rn(b.x, b.y);
    }
}

// ---------------------------------------------------------------------------
// Kernel 1: q/k projection in bf16 (unchanged from round 13 — passing)
// ---------------------------------------------------------------------------
#define QK_LD 72
#define QK_ABUF (64 * QK_LD * 2)
#define QK_BBUF (128 * QK_LD * 2)
#define QK_BUF  (QK_ABUF + QK_BBUF)
#define QK_SMEM_BYTES (2 * QK_BUF)

__global__ void __launch_bounds__(256, 2) proj_qk_kernel()
{
    extern __shared__ char sm[];
    const int which = blockIdx.y;
    const __nv_bfloat16* X = g_xb;
    const __nv_bfloat16* W = which ? g_wkb : g_wqb;

    const int row0 = blockIdx.x * 64;
    const int tid  = threadIdx.x;
    const int warp = tid >> 5;
    const int warpM = warp >> 1;
    const int warpN = warp & 1;

    auto load_chunk = [&](int c) {
        char* As = sm + (c & 1) * QK_BUF;
        char* Bs = As + QK_ABUF;
        #pragma unroll
        for (int i = 0; i < 2; i++) {
            int idx = tid + i * 256;
            int r = idx >> 3, cb = (idx & 7) << 4;
            cp16p(As + r * 144 + cb,
                  (const char*)(X + (size_t)(row0 + r) * D_EMBED + c * 64) + cb);
        }
        #pragma unroll
        for (int i = 0; i < 4; i++) {
            int idx = tid + i * 256;
            int r = idx >> 3, cb = (idx & 7) << 4;
            cp16p(Bs + r * 144 + cb,
                  (const char*)(W + (size_t)r * D_EMBED + c * 64) + cb);
        }
        CP_COMMIT();
    };

    wmma::fragment<wmma::accumulator, 16, 16, 16, float> acc[4];
    #pragma unroll
    for (int f = 0; f < 4; f++) wmma::fill_fragment(acc[f], 0.0f);

    load_chunk(0);
    for (int c = 0; c < 16; c++) {
        if (c + 1 < 16) { load_chunk(c + 1); CP_WAIT1(); } else { CP_WAIT0(); }
        __syncthreads();
        __nv_bfloat16* As = (__nv_bfloat16*)(sm + (c & 1) * QK_BUF);
        __nv_bfloat16* Bs = (__nv_bfloat16*)((char*)As + QK_ABUF);
        #pragma unroll
        for (int kk = 0; kk < 4; kk++) {
            wmma::fragment<wmma::matrix_a, 16, 16, 16, __nv_bfloat16,
                           wmma::row_major> a;
            wmma::load_matrix_sync(a, As + warpM * 16 * QK_LD + kk * 16, QK_LD);
            #pragma unroll
            for (int f = 0; f < 4; f++) {
                wmma::fragment<wmma::matrix_b, 16, 16, 16, __nv_bfloat16,
                               wmma::col_major> b;
                wmma::load_matrix_sync(b, Bs + (warpN * 64 + f * 16) * QK_LD + kk * 16, QK_LD);
                wmma::mma_sync(acc[f], a, b, acc[f]);
            }
        }
        __syncthreads();
    }

    float* stage = (float*)sm;
    #pragma unroll
    for (int f = 0; f < 4; f++)
        wmma::store_matrix_sync(stage + warpM * 16 * 132 + warpN * 64 + f * 16,
                                acc[f], 132, wmma::mem_row_major);
    __syncthreads();

    __nv_bfloat16* outb = which ? g_kb : g_qb;
    const float scl = which ? 1.0f : (float)QK_SCALE;
    __nv_bfloat162* ob2 = (__nv_bfloat162*)(outb + (size_t)row0 * D_HEAD);
    #pragma unroll
    for (int i = 0; i < 16; i++) {
        int idx2 = tid + i * 256;
        int r = idx2 >> 6, cc = idx2 & 63;
        float2 t = *(float2*)(stage + r * 132 + cc * 2);
        ob2[idx2] = __floats2bfloat162_rn(t.x * scl, t.y * scl);
    }
}

// ---------------------------------------------------------------------------
// Kernel 2: v projection (TF32, unchanged from round 13 — passing)
// ---------------------------------------------------------------------------
#define PJ_LDA 36
#define PJ_SMEM_BYTES (64 * 132 * 4)

__global__ void __launch_bounds__(256, 2) proj_v_kernel(
    const float* __restrict__ x, const float* __restrict__ Wv)
{
    extern __shared__ float psm[];
    float* As = psm;
    float* Bs = psm + 64 * PJ_LDA;
    __shared__ float cpart[2][128];

    const int row0 = blockIdx.x * 64;
    const int tid  = threadIdx.x;
    const int warp = tid >> 5;
    const int warpM = warp >> 1;
    const int warpN = warp & 1;

    wmma::fragment<wmma::accumulator, 16, 16, 8, float> acc[4];
    #pragma unroll
    for (int f = 0; f < 4; f++) wmma::fill_fragment(acc[f], 0.0f);

    for (int kc = 0; kc < D_EMBED; kc += 32) {
        #pragma unroll
        for (int i = 0; i < 2; i++) {
            int idx4 = tid + i * 256;
            int r = idx4 >> 3, c4 = idx4 & 7;
            *(float4*)(As + r * PJ_LDA + c4 * 4) =
                *(const float4*)(x + (size_t)(row0 + r) * D_EMBED + kc + c4 * 4);
        }
        #pragma unroll
        for (int i = 0; i < 4; i++) {
            int idx4 = tid + i * 256;
            int r = idx4 >> 3, c4 = idx4 & 7;
            *(float4*)(Bs + r * PJ_LDA + c4 * 4) =
                *(const float4*)(Wv + (size_t)r * D_EMBED + kc + c4 * 4);
        }
        __syncthreads();

        #pragma unroll
        for (int kk = 0; kk < 32; kk += 8) {
            wmma::fragment<wmma::matrix_a, 16, 16, 8, wmma::precision::tf32,
                           wmma::row_major> a;
            wmma::load_matrix_sync(a, As + warpM * 16 * PJ_LDA + kk, PJ_LDA);
            #pragma unroll
            for (int t = 0; t < a.num_elements; t++)
                a.x[t] = wmma::__float_to_tf32(a.x[t]);
            #pragma unroll
            for (int f = 0; f < 4; f++) {
                wmma::fragment<wmma::matrix_b, 16, 16, 8, wmma::precision::tf32,
                               wmma::col_major> b;
                wmma::load_matrix_sync(b, Bs + (warpN * 64 + f * 16) * PJ_LDA + kk, PJ_LDA);
                #pragma unroll
                for (int t = 0; t < b.num_elements; t++)
                    b.x[t] = wmma::__float_to_tf32(b.x[t]);
                wmma::mma_sync(acc[f], a, b, acc[f]);
            }
        }
        __syncthreads();
    }

    float* stage = psm;
    #pragma unroll
    for (int f = 0; f < 4; f++)
        wmma::store_matrix_sync(stage + warpM * 16 * 132 + warpN * 64 + f * 16,
                                acc[f], 132, wmma::mem_row_major);
    __syncthreads();

    __nv_bfloat162* ob2 = (__nv_bfloat162*)(g_vb + (size_t)row0 * D_HEAD);
    #pragma unroll
    for (int i = 0; i < 16; i++) {
        int idx2 = tid + i * 256;
        int r = idx2 >> 6, cc = idx2 & 63;
        float2 t = *(float2*)(stage + r * 132 + cc * 2);
        ob2[idx2] = __floats2bfloat162_rn(t.x, t.y);
    }
    {
        const int c = tid & 127, half = tid >> 7;
        float s = 0.f;
        #pragma unroll
        for (int r = 0; r < 32; r++) s += stage[(half * 32 + r) * 132 + c];
        cpart[half][c] = s;
    }
    __syncthreads();
    if (tid < 128)
        g_vpart[blockIdx.x * 128 + tid] = cpart[0][tid] + cpart[1][tid];
}

// ---------------------------------------------------------------------------
// Kernel 3: attention — raw mma.sync m16n8k16, register-resident softmax.
//   O = (Vsum + sum (exp(s)-1) @ V) / (4096 + sum(exp(s)-1))
// CTA = 64 q rows, 128 threads (4 warps x 16 rows). K-tile = 64 keys.
// smem: Q | K0 | K1 | V0 | V1 (64x272B each) + vsum[128]f32.
// S never touches smem: exp/pack in C-register layout -> A-fragments of MMA2.
// ---------------------------------------------------------------------------
#define AT_ROWB 272
#define AQ_OFF  0
#define AK0_OFF 17408
#define AK1_OFF (17408 * 2)
#define AV0_OFF (17408 * 3)
#define AV1_OFF (17408 * 4)
#define AVS_OFF (17408 * 5)
#define ATTN_SMEM_BYTES (17408 * 5 + 512)   // 87552

__global__ void __launch_bounds__(128, 2) attn_kernel(float* __restrict__ out)
{
    extern __shared__ char sm[];
    const uint32_t sb = smem_u32(sm);
    float* vsum_s = (float*)(sm + AVS_OFF);

    const int tid  = threadIdx.x;
    const int warp = tid >> 5;
    const int lane = tid & 31;

    const int b  = blockIdx.x >> 6;
    const int qt = blockIdx.x & 63;

    const __nv_bfloat16* Qg = g_qb + ((size_t)b * SEQ + qt * 64) * D_HEAD;
    const __nv_bfloat16* Kg = g_kb + (size_t)b * SEQ * D_HEAD;
    const __nv_bfloat16* Vg = g_vb + (size_t)b * SEQ * D_HEAD;

    // 64 rows x 256B -> padded 272B rows; 1024 chunks, 8 per thread
    auto load64 = [&](const __nv_bfloat16* src0, uint32_t dstoff) {
        const char* src = (const char*)src0;
        #pragma unroll
        for (int i = 0; i < 8; i++) {
            int idx = tid + i * 128;
            int r = idx >> 4, c = idx & 15;
            cp16(sb + dstoff + r * AT_ROWB + c * 16, src + r * 256 + c * 16);
        }
    };

    // Prologue: {Q}, {K0,V0}
    load64(Qg, AQ_OFF);               CP_COMMIT();
    load64(Kg, AK0_OFF);
    load64(Vg, AV0_OFF);              CP_COMMIT();

    // Vsum for this batch (regular loads, overlap with cp.async)
    {
        float s = 0.f;
        #pragma unroll 8
        for (int i = 0; i < 64; i++) s += g_vpart[(b * 64 + i) * 128 + tid];
        vsum_s[tid] = s;
    }

    // lane-pattern address bases (bytes)
    const uint32_t qbase = (uint32_t)((warp * 16 + (lane & 7) + ((lane & 8) ? 8 : 0)) * AT_ROWB
                                      + ((lane & 16) ? 16 : 0));
    const uint32_t kbase = (uint32_t)(((lane & 7) + ((lane & 16) ? 8 : 0)) * AT_ROWB
                                      + ((lane & 8) ? 16 : 0));
    const uint32_t vbase = (uint32_t)(((lane & 7) + ((lane & 8) ? 8 : 0)) * AT_ROWB
                                      + ((lane & 16) ? 16 : 0));

    CP_WAIT0();
    __syncthreads();

    // Q fragments: qa[kk][0..3] (A-layout via non-trans ldmatrix.x4)
    uint32_t qa[8][4];
    #pragma unroll
    for (int kk = 0; kk < 8; kk++)
        LDSM4(qa[kk][0], qa[kk][1], qa[kk][2], qa[kk][3], sb + AQ_OFF + qbase + kk * 32);

    float oacc[16][4];
    #pragma unroll
    for (int n = 0; n < 16; n++)
        #pragma unroll
        for (int j = 0; j < 4; j++) oacc[n][j] = 0.f;
    float l0 = 0.f, l1 = 0.f;

    for (int kt = 0; kt < NT; kt++) {
        const uint32_t koff = (kt & 1) ? AK1_OFF : AK0_OFF;
        const uint32_t voff = (kt & 1) ? AV1_OFF : AV0_OFF;

        if (kt + 1 < NT) {
            const uint32_t koff2 = (kt & 1) ? AK0_OFF : AK1_OFF;
            const uint32_t voff2 = (kt & 1) ? AV0_OFF : AV1_OFF;
            load64(Kg + (size_t)(kt + 1) * 64 * D_HEAD, koff2);
            load64(Vg + (size_t)(kt + 1) * 64 * D_HEAD, voff2);
            CP_COMMIT();
        }
        if (kt + 1 < NT) { CP_WAIT1(); } else { CP_WAIT0(); }
        __syncthreads();

        // ---- MMA1: S = Q @ K^T in registers ----
        float sacc[8][4];
        #pragma unroll
        for (int n = 0; n < 8; n++)
            #pragma unroll
            for (int j = 0; j < 4; j++) sacc[n][j] = 0.f;

        const uint32_t kb = sb + koff + kbase;
        #pragma unroll
        for (int kk = 0; kk < 8; kk++) {
            #pragma unroll
            for (int ng = 0; ng < 4; ng++) {
                uint32_t b0, b1, b2, b3;
                LDSM4(b0, b1, b2, b3, kb + ng * (16 * AT_ROWB) + kk * 32);
                MMA16816(sacc[2 * ng],     qa[kk], b0, b1);
                MMA16816(sacc[2 * ng + 1], qa[kk], b2, b3);
            }
        }

        // ---- softmax in registers: P' = exp(S)-1, pack to A-fragments ----
        uint32_t pa[4][4];
        #pragma unroll
        for (int n = 0; n < 8; n++) {
            float p0 = __expf(sacc[n][0]) - 1.0f;
            float p1 = __expf(sacc[n][1]) - 1.0f;
            float p2 = __expf(sacc[n][2]) - 1.0f;
            float p3 = __expf(sacc[n][3]) - 1.0f;
            l0 += p0 + p1;
            l1 += p2 + p3;
            pa[n >> 1][(n & 1) * 2 + 0] = packbf(p0, p1);
            pa[n >> 1][(n & 1) * 2 + 1] = packbf(p2, p3);
        }

        // ---- MMA2: O += P' @ V (V via ldmatrix.trans) ----
        const uint32_t vb = sb + voff + vbase;
        #pragma unroll
        for (int k2 = 0; k2 < 4; k2++) {
            #pragma unroll
            for (int ng = 0; ng < 8; ng++) {
                uint32_t b0, b1, b2, b3;
                LDSM4T(b0, b1, b2, b3, vb + k2 * (16 * AT_ROWB) + ng * 32);
                MMA16816(oacc[2 * ng],     pa[k2], b0, b1);
                MMA16816(oacc[2 * ng + 1], pa[k2], b2, b3);
            }
        }
        __syncthreads();   // all warps done with K/V bufs before next prefetch lands
    }

    // ---- epilogue ----
    l0 += __shfl_xor_sync(0xffffffffu, l0, 1);
    l0 += __shfl_xor_sync(0xffffffffu, l0, 2);
    l1 += __shfl_xor_sync(0xffffffffu, l1, 1);
    l1 += __shfl_xor_sync(0xffffffffu, l1, 2);
    const float inv0 = 1.0f / (4096.0f + l0);
    const float inv1 = 1.0f / (4096.0f + l1);

    const size_t row0 = (size_t)b * SEQ + qt * 64 + warp * 16 + (lane >> 2);
    float* o0 = out + row0 * D_HEAD;
    float* o1 = o0 + 8 * D_HEAD;
    #pragma unroll
    for (int n = 0; n < 16; n++) {
        int col = n * 8 + (lane & 3) * 2;
        float vs0 = vsum_s[col], vs1 = vsum_s[col + 1];
        float2 r0 = make_float2((oacc[n][0] + vs0) * inv0, (oacc[n][1] + vs1) * inv0);
        float2 r1 = make_float2((oacc[n][2] + vs0) * inv1, (oacc[n][3] + vs1) * inv1);
        *(float2*)(o0 + col) = r0;
        *(float2*)(o1 + col) = r1;
    }
}

// ---------------------------------------------------------------------------
extern "C" void kernel_launch(void* const* d_in, const int* in_sizes, int n_in,
                              void* d_out, int out_size)
{
    const float* x  = (const float*)d_in[0];
    const float* Wq = (const float*)d_in[1];
    const float* Wk = (const float*)d_in[2];
    const float* Wv = (const float*)d_in[3];
    float* out = (float*)d_out;

    cudaFuncSetAttribute(proj_qk_kernel,
                         cudaFuncAttributeMaxDynamicSharedMemorySize, QK_SMEM_BYTES);
    cudaFuncSetAttribute(proj_v_kernel,
                         cudaFuncAttributeMaxDynamicSharedMemorySize, PJ_SMEM_BYTES);
    cudaFuncSetAttribute(attn_kernel,
                         cudaFuncAttributeMaxDynamicSharedMemorySize, ATTN_SMEM_BYTES);

    round_kernel<<<512, 256>>>(x, Wq, Wk);

    dim3 gridQK(M_TOTAL / 64, 2);
    proj_qk_kernel<<<gridQK, 256, QK_SMEM_BYTES>>>();

    proj_v_kernel<<<M_TOTAL / 64, 256, PJ_SMEM_BYTES>>>(x, Wv);

    attn_kernel<<<BATCH * (SEQ / 64), 128, ATTN_SMEM_BYTES>>>(out);
}